// round 16
// baseline (speedup 1.0000x reference)
#include <cuda_runtime.h>
#include <cuda_bf16.h>
#include <math_constants.h>
#include <cstdint>

// KCRouteEncoder:
//   out = pooled_cid + bias + (pooled_content @ W)     (alphas sum to 1)
// Serialized pool -> gemm (overlap measured harmful; tcgen05 blocked by the
// harness's sm_103 ptx target; BM bracketed -> 64 optimal).
// K1 pool v3: 2 positions per block, unconditional float4 gathers (padding
//     alphas are exactly 0), W-convert folded into first 768 blocks.
// K2 gemm v11: R15 single-barrier pipeline + x4 B-ldmatrix (2 LDSM/ks for B).

#define KLEV   8
#define EMB    256
#define PDIM   768
#define MAXPOS 12800

#define BM 64
#define BN 128
#define BK 64
#define NCHUNK (PDIM / BK)                 // 12
#define NSTAGE 3
#define A_STG_B (BM * 128)                 // 8192
#define W_STG_B (BK * 256)                 // 16384
#define STG_B   (A_STG_B + W_STG_B)        // 24576
#define SMEM_TOTAL (NSTAGE * STG_B)        // 73728 -> 3 CTAs/SM

#define WCONV_BLOCKS (PDIM * EMB / 256)    // 768

__device__ __nv_bfloat16 g_P[(size_t)MAXPOS * PDIM];
__device__ __nv_bfloat16 g_W[(size_t)PDIM * EMB];

__device__ __forceinline__ uint32_t smem_u32(const void* p) {
    return (uint32_t)__cvta_generic_to_shared(p);
}
__device__ __forceinline__ void cp_async16(uint32_t dst, const void* src) {
    asm volatile("cp.async.cg.shared.global [%0], [%1], 16;\n" :: "r"(dst), "l"(src));
}
__device__ __forceinline__ void cp_commit() {
    asm volatile("cp.async.commit_group;\n");
}
template <int N>
__device__ __forceinline__ void cp_wait() {
    asm volatile("cp.async.wait_group %0;\n" :: "n"(N));
}

// ------------------------------------------------ fallback W convert
__global__ void convert_w_kernel(const float* __restrict__ proj_w) {
    int i = blockIdx.x * blockDim.x + threadIdx.x;
    if (i < PDIM * EMB)
        g_W[i] = __float2bfloat16_rn(__ldg(&proj_w[i]));
}

// ------------------------------------------------ K1: pool v3 (2 positions/block)
__global__ void __launch_bounds__(256)
pool_kernel(const int* __restrict__ croutes,
            const float* __restrict__ cid_emb,
            const float* __restrict__ weight,
            const float* __restrict__ content_table,
            const float* __restrict__ proj_w,
            const float* __restrict__ proj_b,
            float* __restrict__ out,
            int npos)
{
    const int t    = threadIdx.x;
    const int pos0 = blockIdx.x * 2;

    if (blockIdx.x < WCONV_BLOCKS) {
        int i = blockIdx.x * 256 + t;
        g_W[i] = __float2bfloat16_rn(__ldg(&proj_w[i]));
    }
    if (pos0 >= npos) return;
    const int  pos1 = pos0 + 1;
    const bool has1 = pos1 < npos;

    __shared__ int   rels[2 * KLEV];
    __shared__ float alph[2 * KLEV];

    if (t < 2 * KLEV) {
        int p = pos0 + (t >> 3);
        if (p >= npos) p = npos - 1;
        rels[t] = croutes[(size_t)p * KLEV + (t & 7)] + 2;   // 0..NUM_C+1
    }
    __syncthreads();

    if (t < 2) {
        float nw[KLEV];
        float m = -CUDART_INF_F;
#pragma unroll
        for (int k = 0; k < KLEV; k++) {
            nw[k] = (rels[t * KLEV + k] != 0) ? __ldg(&weight[k]) : -CUDART_INF_F;
            m = fmaxf(m, nw[k]);
        }
        float s = 0.f, ex[KLEV];
#pragma unroll
        for (int k = 0; k < KLEV; k++) { ex[k] = expf(nw[k] - m); s += ex[k]; }
        float inv = 1.f / s;
#pragma unroll
        for (int k = 0; k < KLEV; k++) alph[t * KLEV + k] = ex[k] * inv;
    }
    __syncthreads();

    float a0[KLEV], a1[KLEV];
    int   r0[KLEV], r1[KLEV];
#pragma unroll
    for (int k = 0; k < KLEV; k++) {
        a0[k] = alph[k];        r0[k] = rels[k];
        a1[k] = alph[KLEV + k]; r1[k] = rels[KLEV + k];
    }

    if (t < 192) {
        // content gather, float4 column t, both positions, UNCONDITIONAL
        const float4* ct = (const float4*)content_table;
        float4 s0 = make_float4(0.f, 0.f, 0.f, 0.f);
        float4 s1 = make_float4(0.f, 0.f, 0.f, 0.f);
#pragma unroll
        for (int k = 0; k < KLEV; k++) {
            float4 v0 = __ldg(ct + (size_t)r0[k] * 192 + t);
            float4 v1 = __ldg(ct + (size_t)r1[k] * 192 + t);
            s0.x = fmaf(a0[k], v0.x, s0.x); s0.y = fmaf(a0[k], v0.y, s0.y);
            s0.z = fmaf(a0[k], v0.z, s0.z); s0.w = fmaf(a0[k], v0.w, s0.w);
            s1.x = fmaf(a1[k], v1.x, s1.x); s1.y = fmaf(a1[k], v1.y, s1.y);
            s1.z = fmaf(a1[k], v1.z, s1.z); s1.w = fmaf(a1[k], v1.w, s1.w);
        }
        {
            __nv_bfloat162 lo = __floats2bfloat162_rn(s0.x, s0.y);
            __nv_bfloat162 hi = __floats2bfloat162_rn(s0.z, s0.w);
            uint2 pk;
            pk.x = *reinterpret_cast<uint32_t*>(&lo);
            pk.y = *reinterpret_cast<uint32_t*>(&hi);
            *reinterpret_cast<uint2*>(g_P + (size_t)pos0 * PDIM + 4 * t) = pk;
        }
        if (has1) {
            __nv_bfloat162 lo = __floats2bfloat162_rn(s1.x, s1.y);
            __nv_bfloat162 hi = __floats2bfloat162_rn(s1.z, s1.w);
            uint2 pk;
            pk.x = *reinterpret_cast<uint32_t*>(&lo);
            pk.y = *reinterpret_cast<uint32_t*>(&hi);
            *reinterpret_cast<uint2*>(g_P + (size_t)pos1 * PDIM + 4 * t) = pk;
        }
    } else {
        // cid gather + bias, float4 column u, both positions
        const int u = t - 192;
        const float4* cd = (const float4*)cid_emb;
        float4 bias = __ldg(((const float4*)proj_b) + u);
        float4 s0 = bias, s1 = bias;
#pragma unroll
        for (int k = 0; k < KLEV; k++) {
            // weight-zero guard for pad rows (rel 0/1 -> zero concept rows)
            int   i0 = r0[k] - 2; float w0 = (i0 >= 0) ? a0[k] : 0.f; if (i0 < 0) i0 = 0;
            int   i1 = r1[k] - 2; float w1 = (i1 >= 0) ? a1[k] : 0.f; if (i1 < 0) i1 = 0;
            float4 v0 = __ldg(cd + (size_t)i0 * 64 + u);
            float4 v1 = __ldg(cd + (size_t)i1 * 64 + u);
            s0.x = fmaf(w0, v0.x, s0.x); s0.y = fmaf(w0, v0.y, s0.y);
            s0.z = fmaf(w0, v0.z, s0.z); s0.w = fmaf(w0, v0.w, s0.w);
            s1.x = fmaf(w1, v1.x, s1.x); s1.y = fmaf(w1, v1.y, s1.y);
            s1.z = fmaf(w1, v1.z, s1.z); s1.w = fmaf(w1, v1.w, s1.w);
        }
        *reinterpret_cast<float4*>(out + (size_t)pos0 * EMB + 4 * u) = s0;
        if (has1)
            *reinterpret_cast<float4*>(out + (size_t)pos1 * EMB + 4 * u) = s1;
    }
}

// ------------------------------------------------ K2: GEMM v11
// block (bx, by): rows [64bx,64bx+64), cols [128by, 128by+128)
// 8 warps = 2(M) x 4(N): wm = warp&1 (32 rows), wn = warp>>1 (32 cols)
__global__ void __launch_bounds__(256, 3)
gemm_kernel(float* __restrict__ out, int npos)
{
    extern __shared__ __align__(16) char smem[];

    const int t    = threadIdx.x;
    const int warp = t >> 5;
    const int lane = t & 31;
    const int wm   = warp & 1;
    const int wn   = warp >> 1;
    const int blockRow = blockIdx.x * BM;
    const int nbase    = blockIdx.y * BN;

    float c[2][4][4];
#pragma unroll
    for (int mf = 0; mf < 2; mf++)
#pragma unroll
        for (int nf = 0; nf < 4; nf++)
#pragma unroll
            for (int i = 0; i < 4; i++) c[mf][nf][i] = 0.f;

    // A: 64 rows x 8 chunks of 16B = 512; 2 per thread (u = t, t+256)
    const int a_row0 = t >> 3,         a_ch0 = t & 7;
    const int a_row1 = (t + 256) >> 3, a_ch1 = t & 7;
    int gr0 = blockRow + a_row0; if (gr0 >= npos) gr0 = npos - 1;
    int gr1 = blockRow + a_row1; if (gr1 >= npos) gr1 = npos - 1;
    const __nv_bfloat16* a_src0 = g_P + (size_t)gr0 * PDIM + a_ch0 * 8;
    const __nv_bfloat16* a_src1 = g_P + (size_t)gr1 * PDIM + a_ch1 * 8;
    const uint32_t a_off0 = a_row0 * 128 + ((a_ch0 ^ (a_row0 & 7)) * 16);
    const uint32_t a_off1 = a_row1 * 128 + ((a_ch1 ^ (a_row1 & 7)) * 16);

    auto load_chunk = [&](int kc, int stg) {
        char* base = smem + stg * STG_B;
        cp_async16(smem_u32(base + a_off0), a_src0 + kc * BK);
        cp_async16(smem_u32(base + a_off1), a_src1 + kc * BK);
        char* Wb = base + A_STG_B;
#pragma unroll
        for (int i = 0; i < 4; i++) {
            int u  = t + i * 256;             // 0..1023
            int wr = u >> 4, wc = u & 15;     // row 0..63, chunk 0..15
            cp_async16(smem_u32(Wb + wr * 256 + ((wc ^ (wr & 7)) * 16)),
                       g_W + (size_t)(kc * BK + wr) * EMB + nbase + wc * 8);
        }
        cp_commit();
    };

    load_chunk(0, 0);
    load_chunk(1, 1);

    for (int kc = 0; kc < NCHUNK; kc++) {
        if (kc + 1 < NCHUNK) cp_wait<1>(); else cp_wait<0>();
        __syncthreads();   // also proves all warps finished compute(kc-1)

        if (kc + 2 < NCHUNK)
            load_chunk(kc + 2, (kc + 2) % NSTAGE);

        const char* As = smem + (kc % NSTAGE) * STG_B;
        const char* Ws = As + A_STG_B;

#pragma unroll
        for (int ks = 0; ks < BK / 16; ks++) {
            uint32_t a[2][4];
#pragma unroll
            for (int mf = 0; mf < 2; mf++) {
                int row = wm * 32 + mf * 16 + (lane & 15);
                int ch  = ks * 2 + (lane >> 4);
                uint32_t addr = smem_u32(As + row * 128 + ((ch ^ (row & 7)) * 16));
                asm volatile("ldmatrix.sync.aligned.m8n8.x4.shared.b16 {%0,%1,%2,%3}, [%4];\n"
                             : "=r"(a[mf][0]), "=r"(a[mf][1]), "=r"(a[mf][2]), "=r"(a[mf][3])
                             : "r"(addr));
            }
            uint32_t b[4][2];
#pragma unroll
            for (int np = 0; np < 2; np++) {
                // x4.trans: lanes 0-15 -> chunk (wn*4+np*2), lanes 16-31 -> +1
                int row = ks * 16 + (lane & 15);
                int ch  = wn * 4 + np * 2 + (lane >> 4);
                uint32_t addr = smem_u32(Ws + row * 256 + ((ch ^ (row & 7)) * 16));
                asm volatile("ldmatrix.sync.aligned.m8n8.x4.trans.shared.b16 {%0,%1,%2,%3}, [%4];\n"
                             : "=r"(b[np * 2][0]),     "=r"(b[np * 2][1]),
                               "=r"(b[np * 2 + 1][0]), "=r"(b[np * 2 + 1][1])
                             : "r"(addr));
            }
#pragma unroll
            for (int mf = 0; mf < 2; mf++)
#pragma unroll
                for (int nf = 0; nf < 4; nf++) {
                    asm volatile(
                        "mma.sync.aligned.m16n8k16.row.col.f32.bf16.bf16.f32 "
                        "{%0,%1,%2,%3}, {%4,%5,%6,%7}, {%8,%9}, {%0,%1,%2,%3};\n"
                        : "+f"(c[mf][nf][0]), "+f"(c[mf][nf][1]),
                          "+f"(c[mf][nf][2]), "+f"(c[mf][nf][3])
                        : "r"(a[mf][0]), "r"(a[mf][1]), "r"(a[mf][2]), "r"(a[mf][3]),
                          "r"(b[nf][0]), "r"(b[nf][1]));
                }
        }
    }

    // epilogue: out += C
#pragma unroll
    for (int mf = 0; mf < 2; mf++) {
#pragma unroll
        for (int nf = 0; nf < 4; nf++) {
            int col  = nbase + wn * 32 + nf * 8 + (lane & 3) * 2;
            int row0 = blockRow + wm * 32 + mf * 16 + (lane >> 2);
            if (row0 < npos) {
                float2* o = reinterpret_cast<float2*>(&out[(size_t)row0 * EMB + col]);
                float2 v = *o;
                v.x += c[mf][nf][0]; v.y += c[mf][nf][1];
                *o = v;
            }
            int row1 = row0 + 8;
            if (row1 < npos) {
                float2* o = reinterpret_cast<float2*>(&out[(size_t)row1 * EMB + col]);
                float2 v = *o;
                v.x += c[mf][nf][2]; v.y += c[mf][nf][3];
                *o = v;
            }
        }
    }
}

// ------------------------------------------------ launch
extern "C" void kernel_launch(void* const* d_in, const int* in_sizes, int n_in,
                              void* d_out, int out_size)
{
    const int*   croutes       = (const int*)d_in[0];
    // d_in[1] = tailcs (unused)
    const float* cid_emb       = (const float*)d_in[2];
    const float* weight        = (const float*)d_in[3];
    const float* content_table = (const float*)d_in[4];
    const float* proj_w        = (const float*)d_in[5];
    const float* proj_b        = (const float*)d_in[6];
    float*       out           = (float*)d_out;

    int npos = in_sizes[0] / KLEV;
    if (npos > MAXPOS) npos = MAXPOS;

    const int poolBlocks = (npos + 1) / 2;
    if (poolBlocks < WCONV_BLOCKS)   // fold needs >=768 pool blocks
        convert_w_kernel<<<(PDIM * EMB + 255) / 256, 256>>>(proj_w);

    pool_kernel<<<poolBlocks, 256>>>(croutes, cid_emb, weight, content_table,
                                     proj_w, proj_b, out, npos);

    static bool attr_set = false;
    if (!attr_set) {
        cudaFuncSetAttribute(gemm_kernel,
                             cudaFuncAttributeMaxDynamicSharedMemorySize,
                             SMEM_TOTAL);
        attr_set = true;
    }
    dim3 grid((npos + BM - 1) / BM, 2);
    gemm_kernel<<<grid, 256, SMEM_TOTAL>>>(out, npos);
}

// round 17
// speedup vs baseline: 1.0652x; 1.0652x over previous
#include <cuda_runtime.h>
#include <cuda_bf16.h>
#include <math_constants.h>
#include <cstdint>

// KCRouteEncoder:
//   out = pooled_cid + bias + (pooled_content @ W)     (alphas sum to 1)
// Serialized pool -> gemm (overlap measured harmful; tcgen05 blocked by the
// harness's sm_103 ptx target; BM bracketed -> 64; x4.trans B measured slower).
// K1 pool v4: R5 layout (1 pos/block) with UNCONDITIONAL gathers — padding
//     alphas are exactly 0, so the data-dependent branch only broke MLP.
// K2 gemm: R15 verbatim (BM=64 x BN=128 x BK=64, swizzled, single-barrier
//     3-stage pipeline, 3 CTAs/SM, x2.trans B).

#define KLEV   8
#define EMB    256
#define PDIM   768
#define MAXPOS 12800

#define BM 64
#define BN 128
#define BK 64
#define NCHUNK (PDIM / BK)                 // 12
#define NSTAGE 3
#define A_STG_B (BM * 128)                 // 8192
#define W_STG_B (BK * 256)                 // 16384
#define STG_B   (A_STG_B + W_STG_B)        // 24576
#define SMEM_TOTAL (NSTAGE * STG_B)        // 73728 -> 3 CTAs/SM

#define WCONV_BLOCKS (PDIM * EMB / 256)    // 768

__device__ __nv_bfloat16 g_P[(size_t)MAXPOS * PDIM];
__device__ __nv_bfloat16 g_W[(size_t)PDIM * EMB];

__device__ __forceinline__ uint32_t smem_u32(const void* p) {
    return (uint32_t)__cvta_generic_to_shared(p);
}
__device__ __forceinline__ void cp_async16(uint32_t dst, const void* src) {
    asm volatile("cp.async.cg.shared.global [%0], [%1], 16;\n" :: "r"(dst), "l"(src));
}
__device__ __forceinline__ void cp_commit() {
    asm volatile("cp.async.commit_group;\n");
}
template <int N>
__device__ __forceinline__ void cp_wait() {
    asm volatile("cp.async.wait_group %0;\n" :: "n"(N));
}

// ------------------------------------------------ fallback W convert (npos<768 only)
__global__ void convert_w_kernel(const float* __restrict__ proj_w) {
    int i = blockIdx.x * blockDim.x + threadIdx.x;
    if (i < PDIM * EMB)
        g_W[i] = __float2bfloat16_rn(__ldg(&proj_w[i]));
}

// ------------------------------------------------ K1: pool v4
__global__ void __launch_bounds__(256)
pool_kernel(const int* __restrict__ croutes,
            const float* __restrict__ cid_emb,
            const float* __restrict__ weight,
            const float* __restrict__ content_table,
            const float* __restrict__ proj_w,
            const float* __restrict__ proj_b,
            float* __restrict__ out,
            int npos)
{
    const int pos = blockIdx.x;
    const int t   = threadIdx.x;

    if (blockIdx.x < WCONV_BLOCKS) {
        int i = blockIdx.x * 256 + t;
        g_W[i] = __float2bfloat16_rn(__ldg(&proj_w[i]));
    }
    if (pos >= npos) return;

    __shared__ int   rels[KLEV];
    __shared__ float alph[KLEV];

    if (t < KLEV)
        rels[t] = croutes[(size_t)pos * KLEV + t] + 2;   // 0..NUM_C+1, in-bounds
    __syncthreads();

    if (t == 0) {
        float nw[KLEV];
        float m = -CUDART_INF_F;
#pragma unroll
        for (int k = 0; k < KLEV; k++) {
            nw[k] = (rels[k] != 0) ? __ldg(&weight[k]) : -CUDART_INF_F;
            m = fmaxf(m, nw[k]);
        }
        float s = 0.f, ex[KLEV];
#pragma unroll
        for (int k = 0; k < KLEV; k++) { ex[k] = expf(nw[k] - m); s += ex[k]; }
        float inv = 1.f / s;
#pragma unroll
        for (int k = 0; k < KLEV; k++) alph[k] = ex[k] * inv;
    }
    __syncthreads();

    float a[KLEV]; int r[KLEV];
#pragma unroll
    for (int k = 0; k < KLEV; k++) { a[k] = alph[k]; r[k] = rels[k]; }

    if (t < 192) {
        // content gather: UNCONDITIONAL (pad rows carry alpha == 0 exactly)
        const float4* ct = (const float4*)content_table;
        float4 v[KLEV];
#pragma unroll
        for (int k = 0; k < KLEV; k++)
            v[k] = __ldg(ct + (size_t)r[k] * 192 + t);
        float4 s = make_float4(0.f, 0.f, 0.f, 0.f);
#pragma unroll
        for (int k = 0; k < KLEV; k++) {
            s.x = fmaf(a[k], v[k].x, s.x);
            s.y = fmaf(a[k], v[k].y, s.y);
            s.z = fmaf(a[k], v[k].z, s.z);
            s.w = fmaf(a[k], v[k].w, s.w);
        }
        __nv_bfloat162 lo = __floats2bfloat162_rn(s.x, s.y);
        __nv_bfloat162 hi = __floats2bfloat162_rn(s.z, s.w);
        uint2 pk;
        pk.x = *reinterpret_cast<uint32_t*>(&lo);
        pk.y = *reinterpret_cast<uint32_t*>(&hi);
        *reinterpret_cast<uint2*>(g_P + (size_t)pos * PDIM + 4 * t) = pk;
    } else {
        // cid gather + bias: zero-weight guard, clamped index, unconditional load
        const int u = t - 192;
        const float4* cd = (const float4*)cid_emb;
        float  w[KLEV];
        float4 v[KLEV];
#pragma unroll
        for (int k = 0; k < KLEV; k++) {
            int idx = r[k] - 2;
            w[k] = (idx >= 0) ? a[k] : 0.f;
            if (idx < 0) idx = 0;
            v[k] = __ldg(cd + (size_t)idx * 64 + u);
        }
        float4 s = __ldg(((const float4*)proj_b) + u);
#pragma unroll
        for (int k = 0; k < KLEV; k++) {
            s.x = fmaf(w[k], v[k].x, s.x);
            s.y = fmaf(w[k], v[k].y, s.y);
            s.z = fmaf(w[k], v[k].z, s.z);
            s.w = fmaf(w[k], v[k].w, s.w);
        }
        *reinterpret_cast<float4*>(out + (size_t)pos * EMB + 4 * u) = s;
    }
}

// ------------------------------------------------ K2: GEMM (R15 verbatim)
// block (bx, by): rows [64bx,64bx+64), cols [128by, 128by+128)
// 8 warps = 2(M) x 4(N): wm = warp&1 (32 rows), wn = warp>>1 (32 cols)
__global__ void __launch_bounds__(256, 3)
gemm_kernel(float* __restrict__ out, int npos)
{
    extern __shared__ __align__(16) char smem[];

    const int t    = threadIdx.x;
    const int warp = t >> 5;
    const int lane = t & 31;
    const int wm   = warp & 1;
    const int wn   = warp >> 1;
    const int blockRow = blockIdx.x * BM;
    const int nbase    = blockIdx.y * BN;

    float c[2][4][4];
#pragma unroll
    for (int mf = 0; mf < 2; mf++)
#pragma unroll
        for (int nf = 0; nf < 4; nf++)
#pragma unroll
            for (int i = 0; i < 4; i++) c[mf][nf][i] = 0.f;

    // A: 64 rows x 8 chunks of 16B = 512; 2 per thread (u = t, t+256)
    const int a_row0 = t >> 3,         a_ch0 = t & 7;
    const int a_row1 = (t + 256) >> 3, a_ch1 = t & 7;
    int gr0 = blockRow + a_row0; if (gr0 >= npos) gr0 = npos - 1;
    int gr1 = blockRow + a_row1; if (gr1 >= npos) gr1 = npos - 1;
    const __nv_bfloat16* a_src0 = g_P + (size_t)gr0 * PDIM + a_ch0 * 8;
    const __nv_bfloat16* a_src1 = g_P + (size_t)gr1 * PDIM + a_ch1 * 8;
    const uint32_t a_off0 = a_row0 * 128 + ((a_ch0 ^ (a_row0 & 7)) * 16);
    const uint32_t a_off1 = a_row1 * 128 + ((a_ch1 ^ (a_row1 & 7)) * 16);

    auto load_chunk = [&](int kc, int stg) {
        char* base = smem + stg * STG_B;
        cp_async16(smem_u32(base + a_off0), a_src0 + kc * BK);
        cp_async16(smem_u32(base + a_off1), a_src1 + kc * BK);
        char* Wb = base + A_STG_B;
#pragma unroll
        for (int i = 0; i < 4; i++) {
            int u  = t + i * 256;             // 0..1023
            int wr = u >> 4, wc = u & 15;     // row 0..63, chunk 0..15
            cp_async16(smem_u32(Wb + wr * 256 + ((wc ^ (wr & 7)) * 16)),
                       g_W + (size_t)(kc * BK + wr) * EMB + nbase + wc * 8);
        }
        cp_commit();
    };

    load_chunk(0, 0);
    load_chunk(1, 1);

    for (int kc = 0; kc < NCHUNK; kc++) {
        if (kc + 1 < NCHUNK) cp_wait<1>(); else cp_wait<0>();
        __syncthreads();   // also proves all warps finished compute(kc-1)

        if (kc + 2 < NCHUNK)
            load_chunk(kc + 2, (kc + 2) % NSTAGE);

        const char* As = smem + (kc % NSTAGE) * STG_B;
        const char* Ws = As + A_STG_B;

#pragma unroll
        for (int ks = 0; ks < BK / 16; ks++) {
            uint32_t a[2][4];
#pragma unroll
            for (int mf = 0; mf < 2; mf++) {
                int row = wm * 32 + mf * 16 + (lane & 15);
                int ch  = ks * 2 + (lane >> 4);
                uint32_t addr = smem_u32(As + row * 128 + ((ch ^ (row & 7)) * 16));
                asm volatile("ldmatrix.sync.aligned.m8n8.x4.shared.b16 {%0,%1,%2,%3}, [%4];\n"
                             : "=r"(a[mf][0]), "=r"(a[mf][1]), "=r"(a[mf][2]), "=r"(a[mf][3])
                             : "r"(addr));
            }
            uint32_t b[4][2];
#pragma unroll
            for (int nf = 0; nf < 4; nf++) {
                int row = ks * 16 + (lane & 15);
                int ch  = wn * 4 + nf;        // 16B chunk = 8 bf16 cols
                uint32_t addr = smem_u32(Ws + row * 256 + ((ch ^ (row & 7)) * 16));
                asm volatile("ldmatrix.sync.aligned.m8n8.x2.trans.shared.b16 {%0,%1}, [%2];\n"
                             : "=r"(b[nf][0]), "=r"(b[nf][1]) : "r"(addr));
            }
#pragma unroll
            for (int mf = 0; mf < 2; mf++)
#pragma unroll
                for (int nf = 0; nf < 4; nf++) {
                    asm volatile(
                        "mma.sync.aligned.m16n8k16.row.col.f32.bf16.bf16.f32 "
                        "{%0,%1,%2,%3}, {%4,%5,%6,%7}, {%8,%9}, {%0,%1,%2,%3};\n"
                        : "+f"(c[mf][nf][0]), "+f"(c[mf][nf][1]),
                          "+f"(c[mf][nf][2]), "+f"(c[mf][nf][3])
                        : "r"(a[mf][0]), "r"(a[mf][1]), "r"(a[mf][2]), "r"(a[mf][3]),
                          "r"(b[nf][0]), "r"(b[nf][1]));
                }
        }
    }

    // epilogue: out += C
#pragma unroll
    for (int mf = 0; mf < 2; mf++) {
#pragma unroll
        for (int nf = 0; nf < 4; nf++) {
            int col  = nbase + wn * 32 + nf * 8 + (lane & 3) * 2;
            int row0 = blockRow + wm * 32 + mf * 16 + (lane >> 2);
            if (row0 < npos) {
                float2* o = reinterpret_cast<float2*>(&out[(size_t)row0 * EMB + col]);
                float2 v = *o;
                v.x += c[mf][nf][0]; v.y += c[mf][nf][1];
                *o = v;
            }
            int row1 = row0 + 8;
            if (row1 < npos) {
                float2* o = reinterpret_cast<float2*>(&out[(size_t)row1 * EMB + col]);
                float2 v = *o;
                v.x += c[mf][nf][2]; v.y += c[mf][nf][3];
                *o = v;
            }
        }
    }
}

// ------------------------------------------------ launch
extern "C" void kernel_launch(void* const* d_in, const int* in_sizes, int n_in,
                              void* d_out, int out_size)
{
    const int*   croutes       = (const int*)d_in[0];
    // d_in[1] = tailcs (unused)
    const float* cid_emb       = (const float*)d_in[2];
    const float* weight        = (const float*)d_in[3];
    const float* content_table = (const float*)d_in[4];
    const float* proj_w        = (const float*)d_in[5];
    const float* proj_b        = (const float*)d_in[6];
    float*       out           = (float*)d_out;

    int npos = in_sizes[0] / KLEV;
    if (npos > MAXPOS) npos = MAXPOS;

    if (npos < WCONV_BLOCKS)
        convert_w_kernel<<<(PDIM * EMB + 255) / 256, 256>>>(proj_w);

    pool_kernel<<<npos, 256>>>(croutes, cid_emb, weight, content_table,
                               proj_w, proj_b, out, npos);

    static bool attr_set = false;
    if (!attr_set) {
        cudaFuncSetAttribute(gemm_kernel,
                             cudaFuncAttributeMaxDynamicSharedMemorySize,
                             SMEM_TOTAL);
        attr_set = true;
    }
    dim3 grid((npos + BM - 1) / BM, 2);
    gemm_kernel<<<grid, 256, SMEM_TOTAL>>>(out, npos);
}